// round 14
// baseline (speedup 1.0000x reference)
#include <cuda_runtime.h>

// Persistent single-kernel greedy transducer decode. B=32,T=1000,H=640,V=5000.
// Round 13: round-8 geometry + adjacent-column LDG.64 weights + BCH=16 + tn warming.

typedef unsigned long long ull;

constexpr int kB = 32;
constexpr int kT = 1000;
constexpr int kH = 640;
constexpr int kV = 5000;
constexpr int kG = 2560;

constexpr int NBLK = 592;   // 4 blocks/SM x 148 SMs
constexpr int NTHR = 256;

constexpr int HS = 8, DEP = 80;
constexpr int TILES_A = 320;    // 10 vch(512 cols, 2 adj/thread) x 8 hs x 4 bg(8b)
constexpr int TILES_CH = 160;   // 5 jch(512) x 8 hs x 4 bg
constexpr int BCH = 16;         // 16 v-chunks(320) x 32 b = 512 BC-units
constexpr int PT = 3125;        // precompute: 625 rowblocks(8v) x 5 jch

// ---- device globals ----
__device__ __align__(16) float d_xwx[(size_t)kV * kH * 4];
__device__ __align__(16) float d_part[(size_t)HS * kB * kV];       // 5.12MB
__device__ __align__(16) float d_gpart[(size_t)HS * kB * kH * 4];  // 2.62MB
__device__ __align__(16) float d_jointT[kH * kB];
__device__ __align__(16) float d_hT[kH * kB];
__device__ __align__(16) float d_c[kB * kH];
__device__ float d_scores[kB];
__device__ int   d_tok[kB];
__device__ float d_bmax[kB * BCH];
__device__ int   d_bidx[kB * BCH];
__device__ float d_bsum[kB * BCH];
__device__ int   d_bcnt[2][kB];
__device__ float d_sink;

__device__ __align__(128) unsigned g_count[32];
__device__ __align__(128) unsigned g_gen[32];

__device__ __forceinline__ unsigned ld_cg(const unsigned* p) {
    unsigned v;
    asm volatile("ld.global.cg.u32 %0, [%1];" : "=r"(v) : "l"(p));
    return v;
}
__device__ __forceinline__ int ld_cg_i(const int* p) {
    int v;
    asm volatile("ld.global.cg.s32 %0, [%1];" : "=r"(v) : "l"(p));
    return v;
}
__device__ __forceinline__ float ld_cg_f(const float* p) {
    float v;
    asm volatile("ld.global.cg.f32 %0, [%1];" : "=f"(v) : "l"(p));
    return v;
}

__device__ __forceinline__ void grid_barrier() {
    __syncthreads();
    if (threadIdx.x == 0) {
        __threadfence();
        unsigned my = ld_cg(&g_gen[0]);
        if (atomicAdd(&g_count[0], 1u) == (unsigned)(NBLK - 1)) {
            atomicExch(&g_count[0], 0u);
            __threadfence();
            atomicAdd(&g_gen[0], 1u);
        } else {
            while (ld_cg(&g_gen[0]) == my) { __nanosleep(40); }
        }
        __threadfence();
    }
    __syncthreads();
}

// ---- f32x2 helpers ----
__device__ __forceinline__ ull pack2(float w) {
    ull r; asm("mov.b64 %0, {%1, %1};" : "=l"(r) : "f"(w)); return r;
}
__device__ __forceinline__ void ffma2(ull& a, ull s, ull w) {
    asm("fma.rn.f32x2 %0, %1, %2, %0;" : "+l"(a) : "l"(s), "l"(w));
}
__device__ __forceinline__ float2 unpack2(ull a) {
    float2 f; asm("mov.b64 {%0, %1}, %2;" : "=f"(f.x), "=f"(f.y) : "l"(a)); return f;
}
__device__ __forceinline__ float sigf(float x) { return 1.f / (1.f + expf(-x)); }

// B=8 x C=2 ADJACENT columns over 80 depth rows. Per row: ONE LDG.64 weight
// load (8-deep float2 ring), 2 broadcast LDS.128, 16 FFMA2. wp = even column.
__device__ __forceinline__ void dot80_adj(ull a1[4], ull a2[4], const float (*sA)[8],
                                          const float* __restrict__ wp, size_t ws) {
    const float2* p = reinterpret_cast<const float2*>(wp);
    size_t ws2 = ws >> 1;
    float2 wb[8];
#pragma unroll
    for (int j = 0; j < 8; j++) wb[j] = p[j * ws2];
    const float2* fp = p + 8 * ws2;
#pragma unroll
    for (int g = 0; g < DEP; ++g) {
        float2 w = wb[g & 7];
        if (g < DEP - 8) { wb[g & 7] = *fp; fp += ws2; }
        ull W1 = pack2(w.x), W2 = pack2(w.y);
        const double2* sp = reinterpret_cast<const double2*>(sA[g]);
        double2 q0 = sp[0], q1 = sp[1];
        ull s0 = __double_as_longlong(q0.x);
        ull s1 = __double_as_longlong(q0.y);
        ull s2 = __double_as_longlong(q1.x);
        ull s3 = __double_as_longlong(q1.y);
        ffma2(a1[0], s0, W1); ffma2(a1[1], s1, W1);
        ffma2(a1[2], s2, W1); ffma2(a1[3], s3, W1);
        ffma2(a2[0], s0, W2); ffma2(a2[1], s1, W2);
        ffma2(a2[2], s2, W2); ffma2(a2[3], s3, W2);
    }
}

// Strided C=2 version (precompute only; proven).
__device__ __forceinline__ void dot80_2(ull a1[4], ull a2[4], const float (*sA)[8],
                                        const float* __restrict__ w1p,
                                        const float* __restrict__ w2p, size_t ws) {
    float b1[8], b2[8];
#pragma unroll
    for (int j = 0; j < 8; j++) { b1[j] = w1p[j * ws]; b2[j] = w2p[j * ws]; }
    const float* f1 = w1p + 8 * ws;
    const float* f2 = w2p + 8 * ws;
#pragma unroll
    for (int g = 0; g < DEP; ++g) {
        float c1 = b1[g & 7], c2 = b2[g & 7];
        if (g < DEP - 8) { b1[g & 7] = *f1; f1 += ws; b2[g & 7] = *f2; f2 += ws; }
        ull W1 = pack2(c1), W2 = pack2(c2);
        const double2* sp = reinterpret_cast<const double2*>(sA[g]);
        double2 q0 = sp[0], q1 = sp[1];
        ull s0 = __double_as_longlong(q0.x);
        ull s1 = __double_as_longlong(q0.y);
        ull s2 = __double_as_longlong(q1.x);
        ull s3 = __double_as_longlong(q1.y);
        ffma2(a1[0], s0, W1); ffma2(a1[1], s1, W1);
        ffma2(a1[2], s2, W1); ffma2(a1[3], s3, W1);
        ffma2(a2[0], s0, W2); ffma2(a2[1], s1, W2);
        ffma2(a2[2], s2, W2); ffma2(a2[3], s3, W2);
    }
}

__device__ __forceinline__ void fill_T8(float (*dst)[8], const float* __restrict__ srcT,
                                        int bg, int hbase) {
    for (int idx = threadIdx.x; idx < DEP * 8; idx += NTHR) {
        int hh = idx >> 3, bb = idx & 7;
        dst[hh][bb] = srcT[(hbase + hh) * kB + bg * 8 + bb];
    }
}

// ---- A tile: jointT @ Wc -> d_part (adjacent column pair) ----
__device__ void A_tile(int tt, float (*sA)[8], const float* __restrict__ Wc) {
    int hs = tt & 7, vch = (tt >> 3) % 10, bg = tt / 80;
    int hbase = hs * DEP;
    fill_T8(sA, d_jointT, bg, hbase);
    __syncthreads();
    int v = vch * 512 + 2 * threadIdx.x;        // even; v,v+1 both valid iff v<kV
    if (v < kV) {
        ull a1[4] = {0, 0, 0, 0}, a2[4] = {0, 0, 0, 0};
        dot80_adj(a1, a2, sA, Wc + (size_t)hbase * kV + v, kV);
        size_t rb = (size_t)(hs * kB + bg * 8) * kV + v;
#pragma unroll
        for (int i = 0; i < 4; i++) {
            float2 f1 = unpack2(a1[i]);          // col v,   b 2i/2i+1
            float2 f2 = unpack2(a2[i]);          // col v+1
            *reinterpret_cast<float2*>(&d_part[rb + (size_t)(2 * i) * kV]) =
                make_float2(f1.x, f2.x);
            *reinterpret_cast<float2*>(&d_part[rb + (size_t)(2 * i + 1) * kV]) =
                make_float2(f1.y, f2.y);
        }
    }
}

// ---- CH tile: hT @ Wh -> d_gpart (adjacent pair; never crosses a gate) ----
__device__ void CH_tile(int u, float (*sA)[8], const float* __restrict__ Wh) {
    int hs = u & 7, jch = (u >> 3) % 5, bg = u / 40;
    int hbase = hs * DEP;
    fill_T8(sA, d_hT, bg, hbase);
    __syncthreads();
    int j = jch * 512 + 2 * threadIdx.x;         // even
    ull a1[4] = {0, 0, 0, 0}, a2[4] = {0, 0, 0, 0};
    dot80_adj(a1, a2, sA, Wh + (size_t)hbase * kG + j, kG);
    int gate = j / kH, k = j - gate * kH;        // k even; k+1 same gate
#pragma unroll
    for (int i = 0; i < 4; i++) {
        float2 f1 = unpack2(a1[i]);
        float2 f2 = unpack2(a2[i]);
        int b0 = bg * 8 + 2 * i;
        d_gpart[(((size_t)hs * kB + b0) * kH + k) * 4 + gate] = f1.x;
        d_gpart[(((size_t)hs * kB + b0 + 1) * kH + k) * 4 + gate] = f1.y;
        d_gpart[(((size_t)hs * kB + b0) * kH + k + 1) * 4 + gate] = f2.x;
        d_gpart[(((size_t)hs * kB + b0 + 1) * kH + k + 1) * 4 + gate] = f2.y;
    }
}

// ---- fused phase: B partial (16 chunks/b) + flag-sync + cooperative C2 ----
__device__ void phaseBC(int t, const float* __restrict__ bc, const float* __restrict__ tn,
                        const float* __restrict__ bias, float* __restrict__ out,
                        float* s_f, int* s_i, float* s_s) {
    int u = blockIdx.x;            // < 512
    int b = u >> 4, ch = u & 15;
    int p = t & 1;
    int v0 = ch * 320;
    int tid = threadIdx.x;

    float m = -1e30f; int mi = 0x7fffffff; float se = 0.f;
    int v = v0 + 4 * tid;
    if (tid < 80 && v < kV) {
        float4 s = *(const float4*)&bc[v];
#pragma unroll
        for (int hs = 0; hs < HS; hs++) {
            float4 pp = *(const float4*)&d_part[((size_t)(hs * kB + b)) * kV + v];
            s.x += pp.x; s.y += pp.y; s.z += pp.z; s.w += pp.w;
        }
        se = expf(s.x) + expf(s.y) + expf(s.z) + expf(s.w);
        m = s.x; mi = v;
        if (s.y > m) { m = s.y; mi = v + 1; }
        if (s.z > m) { m = s.z; mi = v + 2; }
        if (s.w > m) { m = s.w; mi = v + 3; }
    }
    s_f[tid] = m; s_i[tid] = mi; s_s[tid] = se;
    __syncthreads();
    for (int w = 128; w; w >>= 1) {
        if (tid < w) {
            float om = s_f[tid + w]; int oi = s_i[tid + w];
            if (om > s_f[tid] || (om == s_f[tid] && oi < s_i[tid])) { s_f[tid] = om; s_i[tid] = oi; }
            s_s[tid] += s_s[tid + w];
        }
        __syncthreads();
    }
    if (tid == 0) {
        d_bmax[u] = s_f[0]; d_bidx[u] = s_i[0]; d_bsum[u] = s_s[0];
        d_bcnt[p ^ 1][b] = 0;
        __threadfence();
        atomicAdd(&d_bcnt[p][b], 1);
        while (ld_cg_i(&d_bcnt[p][b]) < BCH) { __nanosleep(20); }
    }
    __syncthreads();

    float M = -1e30f; int MI = 0; float S = 0.f;
#pragma unroll
    for (int c = 0; c < BCH; c++) {
        float cm = __ldcg(&d_bmax[b * BCH + c]);
        int ci = __ldcg(&d_bidx[b * BCH + c]);
        S += __ldcg(&d_bsum[b * BCH + c]);
        if (cm > M) { M = cm; MI = ci; }
    }
    int upd = (MI != 0);
    int nt = upd ? MI : ld_cg_i(&d_tok[b]);

    if (t < kT - 1 && tid < 40) {      // this block owns k in [ch*40, ch*40+40)
        int k = ch * 40 + tid;
        float hnew;
        if (upd) {
            float4 a = *(const float4*)&d_xwx[((size_t)nt * kH + k) * 4];
            a.x += bias[k]; a.y += bias[kH + k];
            a.z += bias[2 * kH + k]; a.w += bias[3 * kH + k];
#pragma unroll
            for (int hs = 0; hs < HS; hs++) {
                float4 pp = *(const float4*)&d_gpart[(((size_t)hs * kB + b) * kH + k) * 4];
                a.x += pp.x; a.y += pp.y; a.z += pp.z; a.w += pp.w;
            }
            float cold = d_c[b * kH + k];
            float c2v = sigf(a.y) * cold + sigf(a.x) * tanhf(a.z);
            float h2 = sigf(a.w) * tanhf(c2v);
            d_c[b * kH + k] = c2v;
            d_hT[k * kB + b] = h2;
            hnew = h2;
        } else {
            hnew = d_hT[k * kB + b];
        }
        d_jointT[k * kB + b] = tanhf(tn[((size_t)b * kT + (t + 1)) * kH + k] + hnew);
    }

    if (ch == 0 && tid == 0) {
        float val = M - logf(S);
        float sc = d_scores[b] + (upd ? val : 0.f);
        d_scores[b] = sc;
        if (t == kT - 1) out[b] = sc;
        out[kB + (size_t)b * kT + t] = (float)(upd ? MI : 0);
        if (upd) d_tok[b] = MI;
    }
}

// ---- one-time: xWx = embed @ Wx -> [v][k][gate] ----
__device__ void precompute_xwx(const float* __restrict__ embed, const float* __restrict__ Wx,
                               float (*sA)[8]) {
    for (int tp = blockIdx.x; tp < PT; tp += NBLK) {
        int rb = tp / 5, jch = tp % 5;
        int v0 = rb * 8;
        int tid = threadIdx.x;
        int j1 = jch * 512 + tid, j2 = j1 + 256;
        ull a1[4] = {0, 0, 0, 0}, a2[4] = {0, 0, 0, 0};
        for (int hs = 0; hs < HS; hs++) {
            __syncthreads();
            for (int idx = tid; idx < DEP * 8; idx += NTHR) {
                int hh = idx >> 3, bb = idx & 7;
                sA[hh][bb] = embed[(size_t)(v0 + bb) * kH + hs * DEP + hh];
            }
            __syncthreads();
            dot80_2(a1, a2, sA, Wx + (size_t)(hs * DEP) * kG + j1,
                    Wx + (size_t)(hs * DEP) * kG + j2, kG);
        }
        int g1 = j1 / kH, k1 = j1 - g1 * kH;
        int g2 = j2 / kH, k2 = j2 - g2 * kH;
#pragma unroll
        for (int i = 0; i < 4; i++) {
            float2 f1 = unpack2(a1[i]);
            float2 f2 = unpack2(a2[i]);
            d_xwx[((size_t)(v0 + 2 * i) * kH + k1) * 4 + g1] = f1.x;
            d_xwx[((size_t)(v0 + 2 * i + 1) * kH + k1) * 4 + g1] = f1.y;
            d_xwx[((size_t)(v0 + 2 * i) * kH + k2) * 4 + g2] = f2.x;
            d_xwx[((size_t)(v0 + 2 * i + 1) * kH + k2) * 4 + g2] = f2.y;
        }
        __syncthreads();
    }
}

__device__ void initC2(const float* __restrict__ tn, const float* __restrict__ bias) {
    int gid = blockIdx.x * NTHR + threadIdx.x;
    if (gid >= kB * kH) return;
    int b = gid / kH, k = gid - b * kH;
    float4 a = *(const float4*)&d_xwx[(size_t)k * 4];
    a.x += bias[k]; a.y += bias[kH + k]; a.z += bias[2 * kH + k]; a.w += bias[3 * kH + k];
    float c1 = sigf(a.x) * tanhf(a.z);
    float h1 = sigf(a.w) * tanhf(c1);
    d_c[gid] = c1;
    d_hT[k * kB + b] = h1;
    d_jointT[k * kB + b] = tanhf(tn[(size_t)b * kT * kH + k] + h1);
    if (k == 0) { d_scores[b] = 0.f; d_tok[b] = 0; d_bcnt[0][b] = 0; d_bcnt[1][b] = 0; }
}

__global__ void __launch_bounds__(NTHR, 4)
transducer_kernel(const float* __restrict__ tn, const float* __restrict__ embed,
                  const float* __restrict__ Wx, const float* __restrict__ Wh,
                  const float* __restrict__ bias, const float* __restrict__ Wc,
                  const float* __restrict__ bc, float* __restrict__ out) {
    __shared__ __align__(16) float sA[DEP][8];
    __shared__ float s_f[NTHR];
    __shared__ int   s_i[NTHR];
    __shared__ float s_s[NTHR];

    precompute_xwx(embed, Wx, sA);
    grid_barrier();
    initC2(tn, bias);
    grid_barrier();

    for (int t = 0; t < kT; ++t) {
        // phase 1: A + CH tiles; idle blocks warm next-step tn slice into L2
        if (blockIdx.x < TILES_A) {
            A_tile(blockIdx.x, sA, Wc);
        } else if (t < kT - 1 && blockIdx.x < TILES_A + TILES_CH) {
            CH_tile(blockIdx.x - TILES_A, sA, Wh);
        } else if (t < kT - 1 && blockIdx.x >= TILES_A + TILES_CH) {
            int idx = (blockIdx.x - TILES_A - TILES_CH) * NTHR + threadIdx.x;
            if (idx < kB * kH) {
                int b = idx / kH, k = idx - b * kH;
                float s = ld_cg_f(&tn[((size_t)b * kT + (t + 1)) * kH + k]);
                if (s == 1234567.89f) d_sink = s;   // keep the load alive
            }
        }
        grid_barrier();

        // phase 2: fused B -> cooperative C2 (blocks 0..511)
        if (blockIdx.x < kB * BCH) {
            phaseBC(t, bc, tn, bias, out, s_f, s_i, s_s);
        }
        grid_barrier();
    }
}

extern "C" void kernel_launch(void* const* d_in, const int* in_sizes, int n_in,
                              void* d_out, int out_size) {
    const float* tn    = (const float*)d_in[0];
    const float* embed = (const float*)d_in[1];
    const float* Wx    = (const float*)d_in[2];
    const float* Wh    = (const float*)d_in[3];
    const float* bias  = (const float*)d_in[4];
    const float* Wc    = (const float*)d_in[5];
    const float* bc    = (const float*)d_in[6];
    float* out = (float*)d_out;
    (void)in_sizes; (void)n_in; (void)out_size;
    transducer_kernel<<<NBLK, NTHR>>>(tn, embed, Wx, Wh, bias, Wc, bc, out);
}

// round 15
// speedup vs baseline: 1.2117x; 1.2117x over previous
#include <cuda_runtime.h>

// Persistent single-kernel greedy transducer decode. B=32,T=1000,H=640,V=5000.
// Round 14: round-8 EXACT + (1) 8-leaf tree barrier, (2) adjacent-col LDG.64 weights.

typedef unsigned long long ull;

constexpr int kB = 32;
constexpr int kT = 1000;
constexpr int kH = 640;
constexpr int kV = 5000;
constexpr int kG = 2560;

constexpr int NBLK = 592;   // 4 blocks/SM x 148 SMs
constexpr int NTHR = 256;

constexpr int HS = 8, DEP = 80;
constexpr int TILES_A = 320;    // 10 vch(512 cols, adj pair/thread) x 8 hs x 4 bg(8b)
constexpr int TILES_CH = 160;   // 5 jch(512) x 8 hs x 4 bg
constexpr int BCH = 8;          // 8 v-chunks x 32 b = 256 BC-units
constexpr int PT = 3125;        // precompute: 625 rowblocks(8v) x 5 jch

// ---- device globals ----
__device__ __align__(16) float d_xwx[(size_t)kV * kH * 4];
__device__ __align__(16) float d_part[(size_t)HS * kB * kV];       // 5.12MB
__device__ __align__(16) float d_gpart[(size_t)HS * kB * kH * 4];  // 2.62MB
__device__ __align__(16) float d_jointT[kH * kB];
__device__ __align__(16) float d_hT[kH * kB];
__device__ __align__(16) float d_c[kB * kH];
__device__ float d_scores[kB];
__device__ int   d_tok[kB];
__device__ float d_bmax[kB * BCH];
__device__ int   d_bidx[kB * BCH];
__device__ float d_bsum[kB * BCH];
__device__ int   d_bcnt[2][kB];

// tree barrier state: 8 leaf counters on distinct 128B lines + root + gen
__device__ __align__(128) unsigned g_leaf[8][32];
__device__ __align__(128) unsigned g_root[32];
__device__ __align__(128) unsigned g_gen[32];

__device__ __forceinline__ unsigned ld_cg(const unsigned* p) {
    unsigned v;
    asm volatile("ld.global.cg.u32 %0, [%1];" : "=r"(v) : "l"(p));
    return v;
}
__device__ __forceinline__ int ld_cg_i(const int* p) {
    int v;
    asm volatile("ld.global.cg.s32 %0, [%1];" : "=r"(v) : "l"(p));
    return v;
}

__device__ __forceinline__ void grid_barrier() {
    __syncthreads();
    if (threadIdx.x == 0) {
        __threadfence();
        unsigned my = ld_cg(&g_gen[0]);
        unsigned* leaf = &g_leaf[blockIdx.x & 7][0];
        if (atomicAdd(leaf, 1u) == (unsigned)(NBLK / 8 - 1)) {
            atomicExch(leaf, 0u);
            __threadfence();
            if (atomicAdd(&g_root[0], 1u) == 7u) {
                atomicExch(&g_root[0], 0u);
                __threadfence();
                atomicAdd(&g_gen[0], 1u);
            } else {
                while (ld_cg(&g_gen[0]) == my) { __nanosleep(20); }
            }
        } else {
            while (ld_cg(&g_gen[0]) == my) { __nanosleep(30); }
        }
        __threadfence();
    }
    __syncthreads();
}

// ---- f32x2 helpers ----
__device__ __forceinline__ ull pack2(float w) {
    ull r; asm("mov.b64 %0, {%1, %1};" : "=l"(r) : "f"(w)); return r;
}
__device__ __forceinline__ void ffma2(ull& a, ull s, ull w) {
    asm("fma.rn.f32x2 %0, %1, %2, %0;" : "+l"(a) : "l"(s), "l"(w));
}
__device__ __forceinline__ float2 unpack2(ull a) {
    float2 f; asm("mov.b64 {%0, %1}, %2;" : "=f"(f.x), "=f"(f.y) : "l"(a)); return f;
}
__device__ __forceinline__ float sigf(float x) { return 1.f / (1.f + expf(-x)); }

// B=8 x C=2 ADJACENT columns over 80 depth rows. Per row: ONE LDG.64 weight
// (8-deep float2 ring), 2 broadcast LDS.128, 8 FFMA2. wp must be even column.
__device__ __forceinline__ void dot80_adj(ull a1[4], ull a2[4], const float (*sA)[8],
                                          const float* __restrict__ wp, size_t ws) {
    const float2* p = reinterpret_cast<const float2*>(wp);
    size_t ws2 = ws >> 1;
    float2 wb[8];
#pragma unroll
    for (int j = 0; j < 8; j++) wb[j] = p[j * ws2];
    const float2* fp = p + 8 * ws2;
#pragma unroll
    for (int g = 0; g < DEP; ++g) {
        float2 w = wb[g & 7];
        if (g < DEP - 8) { wb[g & 7] = *fp; fp += ws2; }
        ull W1 = pack2(w.x), W2 = pack2(w.y);
        const double2* sp = reinterpret_cast<const double2*>(sA[g]);
        double2 q0 = sp[0], q1 = sp[1];
        ull s0 = __double_as_longlong(q0.x);
        ull s1 = __double_as_longlong(q0.y);
        ull s2 = __double_as_longlong(q1.x);
        ull s3 = __double_as_longlong(q1.y);
        ffma2(a1[0], s0, W1); ffma2(a1[1], s1, W1);
        ffma2(a1[2], s2, W1); ffma2(a1[3], s3, W1);
        ffma2(a2[0], s0, W2); ffma2(a2[1], s1, W2);
        ffma2(a2[2], s2, W2); ffma2(a2[3], s3, W2);
    }
}

// Strided C=2 version (precompute only; proven).
__device__ __forceinline__ void dot80_2(ull a1[4], ull a2[4], const float (*sA)[8],
                                        const float* __restrict__ w1p,
                                        const float* __restrict__ w2p, size_t ws) {
    float b1[8], b2[8];
#pragma unroll
    for (int j = 0; j < 8; j++) { b1[j] = w1p[j * ws]; b2[j] = w2p[j * ws]; }
    const float* f1 = w1p + 8 * ws;
    const float* f2 = w2p + 8 * ws;
#pragma unroll
    for (int g = 0; g < DEP; ++g) {
        float c1 = b1[g & 7], c2 = b2[g & 7];
        if (g < DEP - 8) { b1[g & 7] = *f1; f1 += ws; b2[g & 7] = *f2; f2 += ws; }
        ull W1 = pack2(c1), W2 = pack2(c2);
        const double2* sp = reinterpret_cast<const double2*>(sA[g]);
        double2 q0 = sp[0], q1 = sp[1];
        ull s0 = __double_as_longlong(q0.x);
        ull s1 = __double_as_longlong(q0.y);
        ull s2 = __double_as_longlong(q1.x);
        ull s3 = __double_as_longlong(q1.y);
        ffma2(a1[0], s0, W1); ffma2(a1[1], s1, W1);
        ffma2(a1[2], s2, W1); ffma2(a1[3], s3, W1);
        ffma2(a2[0], s0, W2); ffma2(a2[1], s1, W2);
        ffma2(a2[2], s2, W2); ffma2(a2[3], s3, W2);
    }
}

__device__ __forceinline__ void fill_T8(float (*dst)[8], const float* __restrict__ srcT,
                                        int bg, int hbase) {
    for (int idx = threadIdx.x; idx < DEP * 8; idx += NTHR) {
        int hh = idx >> 3, bb = idx & 7;
        dst[hh][bb] = srcT[(hbase + hh) * kB + bg * 8 + bb];
    }
}

// ---- A tile: jointT @ Wc -> d_part (adjacent column pair) ----
__device__ void A_tile(int tt, float (*sA)[8], const float* __restrict__ Wc) {
    int hs = tt & 7, vch = (tt >> 3) % 10, bg = tt / 80;
    int hbase = hs * DEP;
    fill_T8(sA, d_jointT, bg, hbase);
    __syncthreads();
    int v = vch * 512 + 2 * threadIdx.x;     // even; if v<kV then v+1<=4999 valid
    if (v < kV) {
        ull a1[4] = {0, 0, 0, 0}, a2[4] = {0, 0, 0, 0};
        dot80_adj(a1, a2, sA, Wc + (size_t)hbase * kV + v, kV);
        size_t rb = (size_t)(hs * kB + bg * 8) * kV + v;
#pragma unroll
        for (int i = 0; i < 4; i++) {
            float2 f1 = unpack2(a1[i]);        // col v,   b 2i/2i+1
            float2 f2 = unpack2(a2[i]);        // col v+1
            *reinterpret_cast<float2*>(&d_part[rb + (size_t)(2 * i) * kV]) =
                make_float2(f1.x, f2.x);
            *reinterpret_cast<float2*>(&d_part[rb + (size_t)(2 * i + 1) * kV]) =
                make_float2(f1.y, f2.y);
        }
    }
}

// ---- CH tile: hT @ Wh -> d_gpart (adjacent pair; never crosses a gate) ----
__device__ void CH_tile(int u, float (*sA)[8], const float* __restrict__ Wh) {
    int hs = u & 7, jch = (u >> 3) % 5, bg = u / 40;
    int hbase = hs * DEP;
    fill_T8(sA, d_hT, bg, hbase);
    __syncthreads();
    int j = jch * 512 + 2 * threadIdx.x;       // even; j+1 same gate (kH even)
    ull a1[4] = {0, 0, 0, 0}, a2[4] = {0, 0, 0, 0};
    dot80_adj(a1, a2, sA, Wh + (size_t)hbase * kG + j, kG);
    int gate = j / kH, k = j - gate * kH;
#pragma unroll
    for (int i = 0; i < 4; i++) {
        float2 f1 = unpack2(a1[i]);
        float2 f2 = unpack2(a2[i]);
        int b0 = bg * 8 + 2 * i;
        d_gpart[(((size_t)hs * kB + b0) * kH + k) * 4 + gate] = f1.x;
        d_gpart[(((size_t)hs * kB + b0 + 1) * kH + k) * 4 + gate] = f1.y;
        d_gpart[(((size_t)hs * kB + b0) * kH + k + 1) * 4 + gate] = f2.x;
        d_gpart[(((size_t)hs * kB + b0 + 1) * kH + k + 1) * 4 + gate] = f2.y;
    }
}

// ---- fused phase: B partial + flag-sync + cooperative C2 (round-8 exact) ----
__device__ void phaseBC(int t, const float* __restrict__ bc, const float* __restrict__ tn,
                        const float* __restrict__ bias, float* __restrict__ out,
                        float* s_f, int* s_i, float* s_s) {
    int u = blockIdx.x;            // < 256
    int b = u >> 3, ch = u & 7;
    int p = t & 1;
    int v0 = ch * 640;
    int tid = threadIdx.x;

    float m = -1e30f; int mi = 0x7fffffff; float se = 0.f;
    int v = v0 + 4 * tid;
    if (tid < 160 && v < kV) {
        float4 s = *(const float4*)&bc[v];
#pragma unroll
        for (int hs = 0; hs < HS; hs++) {
            float4 pp = *(const float4*)&d_part[((size_t)(hs * kB + b)) * kV + v];
            s.x += pp.x; s.y += pp.y; s.z += pp.z; s.w += pp.w;
        }
        se = expf(s.x) + expf(s.y) + expf(s.z) + expf(s.w);
        m = s.x; mi = v;
        if (s.y > m) { m = s.y; mi = v + 1; }
        if (s.z > m) { m = s.z; mi = v + 2; }
        if (s.w > m) { m = s.w; mi = v + 3; }
    }
    s_f[tid] = m; s_i[tid] = mi; s_s[tid] = se;
    __syncthreads();
    for (int w = 128; w; w >>= 1) {
        if (tid < w) {
            float om = s_f[tid + w]; int oi = s_i[tid + w];
            if (om > s_f[tid] || (om == s_f[tid] && oi < s_i[tid])) { s_f[tid] = om; s_i[tid] = oi; }
            s_s[tid] += s_s[tid + w];
        }
        __syncthreads();
    }
    if (tid == 0) {
        d_bmax[u] = s_f[0]; d_bidx[u] = s_i[0]; d_bsum[u] = s_s[0];
        d_bcnt[p ^ 1][b] = 0;
        __threadfence();
        atomicAdd(&d_bcnt[p][b], 1);
        while (ld_cg_i(&d_bcnt[p][b]) < BCH) { __nanosleep(20); }
    }
    __syncthreads();

    float M = -1e30f; int MI = 0; float S = 0.f;
#pragma unroll
    for (int c = 0; c < BCH; c++) {
        float cm = __ldcg(&d_bmax[b * BCH + c]);
        int ci = __ldcg(&d_bidx[b * BCH + c]);
        S += __ldcg(&d_bsum[b * BCH + c]);
        if (cm > M) { M = cm; MI = ci; }
    }
    int upd = (MI != 0);
    int nt = upd ? MI : ld_cg_i(&d_tok[b]);

    if (t < kT - 1 && tid < 80) {      // this block owns k in [ch*80, ch*80+80)
        int k = ch * 80 + tid;
        float hnew;
        if (upd) {
            float4 a = *(const float4*)&d_xwx[((size_t)nt * kH + k) * 4];
            a.x += bias[k]; a.y += bias[kH + k];
            a.z += bias[2 * kH + k]; a.w += bias[3 * kH + k];
#pragma unroll
            for (int hs = 0; hs < HS; hs++) {
                float4 pp = *(const float4*)&d_gpart[(((size_t)hs * kB + b) * kH + k) * 4];
                a.x += pp.x; a.y += pp.y; a.z += pp.z; a.w += pp.w;
            }
            float cold = d_c[b * kH + k];
            float c2v = sigf(a.y) * cold + sigf(a.x) * tanhf(a.z);
            float h2 = sigf(a.w) * tanhf(c2v);
            d_c[b * kH + k] = c2v;
            d_hT[k * kB + b] = h2;
            hnew = h2;
        } else {
            hnew = d_hT[k * kB + b];
        }
        d_jointT[k * kB + b] = tanhf(tn[((size_t)b * kT + (t + 1)) * kH + k] + hnew);
    }

    if (ch == 0 && tid == 0) {
        float val = M - logf(S);
        float sc = d_scores[b] + (upd ? val : 0.f);
        d_scores[b] = sc;
        if (t == kT - 1) out[b] = sc;
        out[kB + (size_t)b * kT + t] = (float)(upd ? MI : 0);
        if (upd) d_tok[b] = MI;
    }
}

// ---- one-time: xWx = embed @ Wx -> [v][k][gate] ----
__device__ void precompute_xwx(const float* __restrict__ embed, const float* __restrict__ Wx,
                               float (*sA)[8]) {
    for (int tp = blockIdx.x; tp < PT; tp += NBLK) {
        int rb = tp / 5, jch = tp % 5;
        int v0 = rb * 8;
        int tid = threadIdx.x;
        int j1 = jch * 512 + tid, j2 = j1 + 256;
        ull a1[4] = {0, 0, 0, 0}, a2[4] = {0, 0, 0, 0};
        for (int hs = 0; hs < HS; hs++) {
            __syncthreads();
            for (int idx = tid; idx < DEP * 8; idx += NTHR) {
                int hh = idx >> 3, bb = idx & 7;
                sA[hh][bb] = embed[(size_t)(v0 + bb) * kH + hs * DEP + hh];
            }
            __syncthreads();
            dot80_2(a1, a2, sA, Wx + (size_t)(hs * DEP) * kG + j1,
                    Wx + (size_t)(hs * DEP) * kG + j2, kG);
        }
        int g1 = j1 / kH, k1 = j1 - g1 * kH;
        int g2 = j2 / kH, k2 = j2 - g2 * kH;
#pragma unroll
        for (int i = 0; i < 4; i++) {
            float2 f1 = unpack2(a1[i]);
            float2 f2 = unpack2(a2[i]);
            d_xwx[((size_t)(v0 + 2 * i) * kH + k1) * 4 + g1] = f1.x;
            d_xwx[((size_t)(v0 + 2 * i + 1) * kH + k1) * 4 + g1] = f1.y;
            d_xwx[((size_t)(v0 + 2 * i) * kH + k2) * 4 + g2] = f2.x;
            d_xwx[((size_t)(v0 + 2 * i + 1) * kH + k2) * 4 + g2] = f2.y;
        }
        __syncthreads();
    }
}

__device__ void initC2(const float* __restrict__ tn, const float* __restrict__ bias) {
    int gid = blockIdx.x * NTHR + threadIdx.x;
    if (gid >= kB * kH) return;
    int b = gid / kH, k = gid - b * kH;
    float4 a = *(const float4*)&d_xwx[(size_t)k * 4];
    a.x += bias[k]; a.y += bias[kH + k]; a.z += bias[2 * kH + k]; a.w += bias[3 * kH + k];
    float c1 = sigf(a.x) * tanhf(a.z);
    float h1 = sigf(a.w) * tanhf(c1);
    d_c[gid] = c1;
    d_hT[k * kB + b] = h1;
    d_jointT[k * kB + b] = tanhf(tn[(size_t)b * kT * kH + k] + h1);
    if (k == 0) { d_scores[b] = 0.f; d_tok[b] = 0; d_bcnt[0][b] = 0; d_bcnt[1][b] = 0; }
}

__global__ void __launch_bounds__(NTHR, 4)
transducer_kernel(const float* __restrict__ tn, const float* __restrict__ embed,
                  const float* __restrict__ Wx, const float* __restrict__ Wh,
                  const float* __restrict__ bias, const float* __restrict__ Wc,
                  const float* __restrict__ bc, float* __restrict__ out) {
    __shared__ __align__(16) float sA[DEP][8];
    __shared__ float s_f[NTHR];
    __shared__ int   s_i[NTHR];
    __shared__ float s_s[NTHR];

    precompute_xwx(embed, Wx, sA);
    grid_barrier();
    initC2(tn, bias);
    grid_barrier();

    for (int t = 0; t < kT; ++t) {
        // phase 1: A (joint@Wc) and CH (h@Wh) in parallel, static 480-tile pool
        if (blockIdx.x < TILES_A) {
            A_tile(blockIdx.x, sA, Wc);
        } else if (t < kT - 1 && blockIdx.x < TILES_A + TILES_CH) {
            CH_tile(blockIdx.x - TILES_A, sA, Wh);
        }
        grid_barrier();

        // phase 2: fused B -> cooperative C2 (blocks 0..255)
        if (blockIdx.x < kB * BCH) {
            phaseBC(t, bc, tn, bias, out, s_f, s_i, s_s);
        }
        grid_barrier();
    }
}

extern "C" void kernel_launch(void* const* d_in, const int* in_sizes, int n_in,
                              void* d_out, int out_size) {
    const float* tn    = (const float*)d_in[0];
    const float* embed = (const float*)d_in[1];
    const float* Wx    = (const float*)d_in[2];
    const float* Wh    = (const float*)d_in[3];
    const float* bias  = (const float*)d_in[4];
    const float* Wc    = (const float*)d_in[5];
    const float* bc    = (const float*)d_in[6];
    float* out = (float*)d_out;
    (void)in_sizes; (void)n_in; (void)out_size;
    transducer_kernel<<<NBLK, NTHR>>>(tn, embed, Wx, Wh, bias, Wc, bc, out);
}

// round 16
// speedup vs baseline: 1.4192x; 1.1712x over previous
#include <cuda_runtime.h>

// Persistent single-kernel greedy transducer decode. B=32,T=1000,H=640,V=5000.
// Round 15: round-6 EXACT base (best: 23.56ms) + shfl B-reduce + faster spin poll.

typedef unsigned long long ull;

constexpr int kB = 32;
constexpr int kT = 1000;
constexpr int kH = 640;
constexpr int kV = 5000;
constexpr int kG = 2560;

constexpr int NBLK = 592;
constexpr int NTHR = 256;

constexpr int HS = 8, DEP = 80;
constexpr int TILES_A = 320;    // 10 vch(512) x 8 hs x 4 bg(8b)
constexpr int TILES_CH = 160;   // 5 jch(512) x 8 hs x 4 bg
constexpr int BCH = 8;          // 8 v-chunks of 640 -> 256 B-units
constexpr int PT = 3125;        // precompute: 625 rowblocks(8v) x 5 jch

// ---- device globals ----
__device__ __align__(16) float d_xwx[(size_t)kV * kH * 4];
__device__ __align__(16) float d_part[(size_t)HS * kB * kV];
__device__ __align__(16) float d_gpart[(size_t)HS * kB * kH * 4];
__device__ __align__(16) float d_jointT[kH * kB];
__device__ __align__(16) float d_hT[kH * kB];
__device__ __align__(16) float d_c[kB * kH];
__device__ float d_scores[kB];
__device__ int   d_tok[kB];
__device__ int   d_newtok[kB];
__device__ int   d_updf[kB];
__device__ float d_bmax[kB * BCH];
__device__ int   d_bidx[kB * BCH];
__device__ float d_bsum[kB * BCH];

__device__ __align__(128) unsigned g_count[32];
__device__ __align__(128) unsigned g_gen[32];

__device__ __forceinline__ unsigned ld_cg(const unsigned* p) {
    unsigned v;
    asm volatile("ld.global.cg.u32 %0, [%1];" : "=r"(v) : "l"(p));
    return v;
}

__device__ __forceinline__ void grid_barrier() {
    __syncthreads();
    if (threadIdx.x == 0) {
        __threadfence();
        unsigned my = ld_cg(&g_gen[0]);
        if (atomicAdd(&g_count[0], 1u) == (unsigned)(NBLK - 1)) {
            atomicExch(&g_count[0], 0u);
            __threadfence();
            atomicAdd(&g_gen[0], 1u);
        } else {
            while (ld_cg(&g_gen[0]) == my) { __nanosleep(25); }
        }
        __threadfence();
    }
    __syncthreads();
}

// ---- f32x2 helpers ----
__device__ __forceinline__ ull pack2(float w) {
    ull r; asm("mov.b64 %0, {%1, %1};" : "=l"(r) : "f"(w)); return r;
}
__device__ __forceinline__ void ffma2(ull& a, ull s, ull w) {
    asm("fma.rn.f32x2 %0, %1, %2, %0;" : "+l"(a) : "l"(s), "l"(w));
}
__device__ __forceinline__ float2 unpack2(ull a) {
    float2 f; asm("mov.b64 {%0, %1}, %2;" : "=f"(f.x), "=f"(f.y) : "l"(a)); return f;
}
__device__ __forceinline__ float sigf(float x) { return 1.f / (1.f + expf(-x)); }

// 2-column x 8-batch dot over 80 depth rows, 8-row weight prefetch ring.
__device__ __forceinline__ void dot80_2(ull a1[4], ull a2[4], const float (*sA)[8],
                                        const float* __restrict__ w1p,
                                        const float* __restrict__ w2p, size_t ws) {
    float b1[8], b2[8];
#pragma unroll
    for (int j = 0; j < 8; j++) { b1[j] = w1p[j * ws]; b2[j] = w2p[j * ws]; }
    const float* f1 = w1p + 8 * ws;
    const float* f2 = w2p + 8 * ws;
#pragma unroll
    for (int g = 0; g < DEP; ++g) {
        float c1 = b1[g & 7], c2 = b2[g & 7];
        if (g < DEP - 8) { b1[g & 7] = *f1; f1 += ws; b2[g & 7] = *f2; f2 += ws; }
        ull W1 = pack2(c1), W2 = pack2(c2);
        const double2* sp = reinterpret_cast<const double2*>(sA[g]);
        double2 q0 = sp[0], q1 = sp[1];
        ull s0 = __double_as_longlong(q0.x);
        ull s1 = __double_as_longlong(q0.y);
        ull s2 = __double_as_longlong(q1.x);
        ull s3 = __double_as_longlong(q1.y);
        ffma2(a1[0], s0, W1); ffma2(a1[1], s1, W1);
        ffma2(a1[2], s2, W1); ffma2(a1[3], s3, W1);
        ffma2(a2[0], s0, W2); ffma2(a2[1], s1, W2);
        ffma2(a2[2], s2, W2); ffma2(a2[3], s3, W2);
    }
}

__device__ __forceinline__ void fill_T8(float (*dst)[8], const float* __restrict__ srcT,
                                        int bg, int hbase) {
    for (int idx = threadIdx.x; idx < DEP * 8; idx += NTHR) {
        int hh = idx >> 3, bb = idx & 7;
        dst[hh][bb] = srcT[(hbase + hh) * kB + bg * 8 + bb];
    }
}

// ---- A tile: jointT @ Wc -> d_part ----
__device__ void A_tile(int tt, float (*sA)[8], const float* __restrict__ Wc) {
    int hs = tt & 7, vch = (tt >> 3) % 10, bg = tt / 80;
    int hbase = hs * DEP;
    fill_T8(sA, d_jointT, bg, hbase);
    __syncthreads();
    int tid = threadIdx.x;
    int v1 = vch * 512 + tid;
    int v2 = v1 + 256;
    bool ok2 = v2 < kV;
    const float* w1 = Wc + (size_t)hbase * kV + v1;
    const float* w2 = Wc + (size_t)hbase * kV + (ok2 ? v2 : v1);
    ull a1[4] = {0, 0, 0, 0}, a2[4] = {0, 0, 0, 0};
    dot80_2(a1, a2, sA, w1, w2, kV);
    size_t rb = (size_t)(hs * kB + bg * 8) * kV;
#pragma unroll
    for (int i = 0; i < 4; i++) {
        float2 f = unpack2(a1[i]);
        d_part[rb + (size_t)(2 * i) * kV + v1] = f.x;
        d_part[rb + (size_t)(2 * i + 1) * kV + v1] = f.y;
    }
    if (ok2) {
#pragma unroll
        for (int i = 0; i < 4; i++) {
            float2 f = unpack2(a2[i]);
            d_part[rb + (size_t)(2 * i) * kV + v2] = f.x;
            d_part[rb + (size_t)(2 * i + 1) * kV + v2] = f.y;
        }
    }
}

// ---- CH tile: hT @ Wh -> d_gpart ----
__device__ void CH_tile(int u, float (*sA)[8], const float* __restrict__ Wh) {
    int hs = u & 7, jch = (u >> 3) % 5, bg = u / 40;
    int hbase = hs * DEP;
    fill_T8(sA, d_hT, bg, hbase);
    __syncthreads();
    int tid = threadIdx.x;
    int j1 = jch * 512 + tid;
    int j2 = j1 + 256;
    const float* w1 = Wh + (size_t)hbase * kG + j1;
    const float* w2 = Wh + (size_t)hbase * kG + j2;
    ull a1[4] = {0, 0, 0, 0}, a2[4] = {0, 0, 0, 0};
    dot80_2(a1, a2, sA, w1, w2, kG);
    int g1 = j1 / kH, k1 = j1 - g1 * kH;
    int g2 = j2 / kH, k2 = j2 - g2 * kH;
#pragma unroll
    for (int i = 0; i < 4; i++) {
        float2 f = unpack2(a1[i]);
        d_gpart[(((size_t)hs * kB + bg * 8 + 2 * i) * kH + k1) * 4 + g1] = f.x;
        d_gpart[(((size_t)hs * kB + bg * 8 + 2 * i + 1) * kH + k1) * 4 + g1] = f.y;
    }
#pragma unroll
    for (int i = 0; i < 4; i++) {
        float2 f = unpack2(a2[i]);
        d_gpart[(((size_t)hs * kB + bg * 8 + 2 * i) * kH + k2) * 4 + g2] = f.x;
        d_gpart[(((size_t)hs * kB + bg * 8 + 2 * i + 1) * kH + k2) * 4 + g2] = f.y;
    }
}

// ---- phase B: per (b,chunk) argmax + sumexp; warp-shfl reduction ----
__device__ void phaseB(const float* __restrict__ bc, float* s_f, int* s_i, float* s_s) {
    int u = blockIdx.x;
    int b = u >> 3, ch = u & 7;
    int v0 = ch * 640;
    int tid = threadIdx.x;

    float m = -1e30f; int mi = 0x7fffffff; float se = 0.f;
    int v = v0 + 4 * tid;
    if (tid < 160 && v < kV) {
        float4 s = *(const float4*)&bc[v];
#pragma unroll
        for (int hs = 0; hs < HS; hs++) {
            float4 p = *(const float4*)&d_part[((size_t)(hs * kB + b)) * kV + v];
            s.x += p.x; s.y += p.y; s.z += p.z; s.w += p.w;
        }
        se = expf(s.x) + expf(s.y) + expf(s.z) + expf(s.w);
        m = s.x; mi = v;
        if (s.y > m) { m = s.y; mi = v + 1; }
        if (s.z > m) { m = s.z; mi = v + 2; }
        if (s.w > m) { m = s.w; mi = v + 3; }
    }
    // intra-warp reduce (lower lane = lower v; ties keep lower index)
#pragma unroll
    for (int o = 16; o; o >>= 1) {
        float om = __shfl_down_sync(0xffffffffu, m, o);
        int oi = __shfl_down_sync(0xffffffffu, mi, o);
        float os = __shfl_down_sync(0xffffffffu, se, o);
        if (om > m || (om == m && oi < mi)) { m = om; mi = oi; }
        se += os;
    }
    int wid = tid >> 5;
    if ((tid & 31) == 0) { s_f[wid] = m; s_i[wid] = mi; s_s[wid] = se; }
    __syncthreads();
    if (tid == 0) {
        float S = se;                      // warp 0 partial (== s_s[0])
#pragma unroll
        for (int w = 1; w < 8; w++) {
            float om = s_f[w]; int oi = s_i[w];
            if (om > m || (om == m && oi < mi)) { m = om; mi = oi; }
            S += s_s[w];
        }
        d_bmax[u] = m; d_bidx[u] = mi; d_bsum[u] = S;
    }
}

// ---- phase C2: combine + LSTM + next joint + emit ----
__device__ void phaseC2(int t, const float* __restrict__ tn, const float* __restrict__ bias,
                        float* __restrict__ out) {
    int gid = blockIdx.x * NTHR + threadIdx.x;
    if (gid >= kB * kH) return;
    int b = gid / kH, k = gid - b * kH;

    float m = -1e30f; int mi = 0;
#pragma unroll
    for (int ch = 0; ch < BCH; ch++) {
        float cm = d_bmax[b * BCH + ch];
        int ci = d_bidx[b * BCH + ch];
        if (cm > m) { m = cm; mi = ci; }
    }
    int upd = (mi != 0);
    int nt = upd ? mi : d_tok[b];

    if (t < kT - 1) {
        float hnew;
        if (upd) {
            float4 a = *(const float4*)&d_xwx[((size_t)nt * kH + k) * 4];
            a.x += bias[k]; a.y += bias[kH + k]; a.z += bias[2 * kH + k]; a.w += bias[3 * kH + k];
#pragma unroll
            for (int hs = 0; hs < HS; hs++) {
                float4 p = *(const float4*)&d_gpart[(((size_t)hs * kB + b) * kH + k) * 4];
                a.x += p.x; a.y += p.y; a.z += p.z; a.w += p.w;
            }
            float cold = d_c[gid];
            float c2 = sigf(a.y) * cold + sigf(a.x) * tanhf(a.z);
            float h2 = sigf(a.w) * tanhf(c2);
            d_c[gid] = c2;
            d_hT[k * kB + b] = h2;
            hnew = h2;
        } else {
            hnew = d_hT[k * kB + b];
        }
        d_jointT[k * kB + b] = tanhf(tn[((size_t)b * kT + (t + 1)) * kH + k] + hnew);
    }

    if (k == 0) {
        float S = 0.f;
#pragma unroll
        for (int ch = 0; ch < BCH; ch++) S += d_bsum[b * BCH + ch];
        float val = m - logf(S);
        float sc = d_scores[b] + (upd ? val : 0.f);
        d_scores[b] = sc;
        if (t == kT - 1) out[b] = sc;
        out[kB + (size_t)b * kT + t] = (float)(upd ? mi : 0);
        if (upd) d_tok[b] = mi;
    }
}

// ---- one-time: xWx = embed @ Wx -> [v][k][gate] ----
__device__ void precompute_xwx(const float* __restrict__ embed, const float* __restrict__ Wx,
                               float (*sA)[8]) {
    for (int tp = blockIdx.x; tp < PT; tp += NBLK) {
        int rb = tp / 5, jch = tp % 5;
        int v0 = rb * 8;
        int tid = threadIdx.x;
        int j1 = jch * 512 + tid, j2 = j1 + 256;
        ull a1[4] = {0, 0, 0, 0}, a2[4] = {0, 0, 0, 0};
        for (int hs = 0; hs < HS; hs++) {
            __syncthreads();
            for (int idx = tid; idx < DEP * 8; idx += NTHR) {
                int hh = idx >> 3, bb = idx & 7;
                sA[hh][bb] = embed[(size_t)(v0 + bb) * kH + hs * DEP + hh];
            }
            __syncthreads();
            dot80_2(a1, a2, sA, Wx + (size_t)(hs * DEP) * kG + j1,
                    Wx + (size_t)(hs * DEP) * kG + j2, kG);
        }
        int g1 = j1 / kH, k1 = j1 - g1 * kH;
        int g2 = j2 / kH, k2 = j2 - g2 * kH;
#pragma unroll
        for (int i = 0; i < 4; i++) {
            float2 f1 = unpack2(a1[i]);
            float2 f2 = unpack2(a2[i]);
            d_xwx[((size_t)(v0 + 2 * i) * kH + k1) * 4 + g1] = f1.x;
            d_xwx[((size_t)(v0 + 2 * i + 1) * kH + k1) * 4 + g1] = f1.y;
            d_xwx[((size_t)(v0 + 2 * i) * kH + k2) * 4 + g2] = f2.x;
            d_xwx[((size_t)(v0 + 2 * i + 1) * kH + k2) * 4 + g2] = f2.y;
        }
        __syncthreads();
    }
}

__device__ void initC2(const float* __restrict__ tn, const float* __restrict__ bias) {
    int gid = blockIdx.x * NTHR + threadIdx.x;
    if (gid >= kB * kH) return;
    int b = gid / kH, k = gid - b * kH;
    float4 a = *(const float4*)&d_xwx[(size_t)k * 4];
    a.x += bias[k]; a.y += bias[kH + k]; a.z += bias[2 * kH + k]; a.w += bias[3 * kH + k];
    float c1 = sigf(a.x) * tanhf(a.z);
    float h1 = sigf(a.w) * tanhf(c1);
    d_c[gid] = c1;
    d_hT[k * kB + b] = h1;
    d_jointT[k * kB + b] = tanhf(tn[(size_t)b * kT * kH + k] + h1);
    if (k == 0) { d_scores[b] = 0.f; d_tok[b] = 0; }
}

__global__ void __launch_bounds__(NTHR, 4)
transducer_kernel(const float* __restrict__ tn, const float* __restrict__ embed,
                  const float* __restrict__ Wx, const float* __restrict__ Wh,
                  const float* __restrict__ bias, const float* __restrict__ Wc,
                  const float* __restrict__ bc, float* __restrict__ out) {
    __shared__ __align__(16) float sA[DEP][8];
    __shared__ float s_f[NTHR];
    __shared__ int   s_i[NTHR];
    __shared__ float s_s[NTHR];

    precompute_xwx(embed, Wx, sA);
    grid_barrier();
    initC2(tn, bias);
    grid_barrier();

    for (int t = 0; t < kT; ++t) {
        if (blockIdx.x < TILES_A) A_tile(blockIdx.x, sA, Wc);
        grid_barrier();
        if (blockIdx.x < kB * BCH) {
            phaseB(bc, s_f, s_i, s_s);
        } else if (t < kT - 1 && blockIdx.x < kB * BCH + TILES_CH) {
            CH_tile(blockIdx.x - kB * BCH, sA, Wh);
        }
        grid_barrier();
        phaseC2(t, tn, bias, out);
        grid_barrier();
    }
}

extern "C" void kernel_launch(void* const* d_in, const int* in_sizes, int n_in,
                              void* d_out, int out_size) {
    const float* tn    = (const float*)d_in[0];
    const float* embed = (const float*)d_in[1];
    const float* Wx    = (const float*)d_in[2];
    const float* Wh    = (const float*)d_in[3];
    const float* bias  = (const float*)d_in[4];
    const float* Wc    = (const float*)d_in[5];
    const float* bc    = (const float*)d_in[6];
    float* out = (float*)d_out;
    (void)in_sizes; (void)n_in; (void)out_size;
    transducer_kernel<<<NBLK, NTHR>>>(tn, embed, Wx, Wh, bias, Wc, bc, out);
}

// round 17
// speedup vs baseline: 1.6406x; 1.1560x over previous
#include <cuda_runtime.h>

// Persistent single-kernel greedy transducer decode. B=32,T=1000,H=640,V=5000.
// Round 16: dataflow flags replace 2 of 3 per-step grid barriers. Compute kernels
// (dot80_2, A/CH tiles, shfl B-reduce, C2 math) identical to round-15 best.
// Roles: blocks 0-319 = A tile + B unit; 320-479 = CH tile + (first 128) C2 unit.

typedef unsigned long long ull;

constexpr int kB = 32;
constexpr int kT = 1000;
constexpr int kH = 640;
constexpr int kV = 5000;
constexpr int kG = 2560;

constexpr int NBLK = 480;
constexpr int NTHR = 256;

constexpr int HS = 8, DEP = 80;
constexpr int PT = 3125;        // precompute: 625 rowblocks(8v) x 5 jch

// ---- device globals ----
__device__ __align__(16) float d_xwx[(size_t)kV * kH * 4];
__device__ __align__(16) float d_part[(size_t)HS * kB * kV];
__device__ __align__(16) float d_gpart[(size_t)HS * kB * kH * 4];
__device__ __align__(16) float d_jointT[kH * kB];
__device__ __align__(16) float d_hT[kH * kB];
__device__ __align__(16) float d_c[kB * kH];
__device__ float d_scores[kB];
__device__ int   d_tok[kB];
__device__ float d_bmax[kB * 10];
__device__ int   d_bidx[kB * 10];
__device__ float d_bsum[kB * 10];

// dataflow counters (parity ping-pong; each padded to its own 128B line)
__device__ unsigned f_joint[2][32][32];   // [p][hs*4+bg]: 8 arrivals (C2)
__device__ unsigned f_part[2][10][32];    // [p][vch]:     32 arrivals (A tiles)
__device__ unsigned f_gp[2][32];          // [p]:          160 arrivals (CH tiles)
__device__ unsigned f_b[2][32][32];       // [p][b]:       10 arrivals (B units)

__device__ __align__(128) unsigned g_count[32];
__device__ __align__(128) unsigned g_gen[32];

__device__ __forceinline__ unsigned ld_cg(const unsigned* p) {
    unsigned v;
    asm volatile("ld.global.cg.u32 %0, [%1];" : "=r"(v) : "l"(p));
    return v;
}

__device__ __forceinline__ void grid_barrier() {
    __syncthreads();
    if (threadIdx.x == 0) {
        __threadfence();
        unsigned my = ld_cg(&g_gen[0]);
        if (atomicAdd(&g_count[0], 1u) == (unsigned)(NBLK - 1)) {
            atomicExch(&g_count[0], 0u);
            __threadfence();
            atomicAdd(&g_gen[0], 1u);
        } else {
            while (ld_cg(&g_gen[0]) == my) { __nanosleep(25); }
        }
        __threadfence();
    }
    __syncthreads();
}

// block-wide wait until *c >= tgt (producer did threadfence before atomicAdd)
__device__ __forceinline__ void wait_cnt(const unsigned* c, unsigned tgt) {
    if (threadIdx.x == 0) {
        while (ld_cg(c) < tgt) { __nanosleep(20); }
        __threadfence();
    }
    __syncthreads();
}
// block-wide arrive (after all threads' writes)
__device__ __forceinline__ void arrive_cnt(unsigned* c) {
    __syncthreads();
    if (threadIdx.x == 0) { __threadfence(); atomicAdd(c, 1u); }
}

// ---- f32x2 helpers ----
__device__ __forceinline__ ull pack2(float w) {
    ull r; asm("mov.b64 %0, {%1, %1};" : "=l"(r) : "f"(w)); return r;
}
__device__ __forceinline__ void ffma2(ull& a, ull s, ull w) {
    asm("fma.rn.f32x2 %0, %1, %2, %0;" : "+l"(a) : "l"(s), "l"(w));
}
__device__ __forceinline__ float2 unpack2(ull a) {
    float2 f; asm("mov.b64 {%0, %1}, %2;" : "=f"(f.x), "=f"(f.y) : "l"(a)); return f;
}
__device__ __forceinline__ float sigf(float x) { return 1.f / (1.f + expf(-x)); }

// 2-column x 8-batch dot over 80 depth rows, 8-row weight prefetch ring.
__device__ __forceinline__ void dot80_2(ull a1[4], ull a2[4], const float (*sA)[8],
                                        const float* __restrict__ w1p,
                                        const float* __restrict__ w2p, size_t ws) {
    float b1[8], b2[8];
#pragma unroll
    for (int j = 0; j < 8; j++) { b1[j] = w1p[j * ws]; b2[j] = w2p[j * ws]; }
    const float* f1 = w1p + 8 * ws;
    const float* f2 = w2p + 8 * ws;
#pragma unroll
    for (int g = 0; g < DEP; ++g) {
        float c1 = b1[g & 7], c2 = b2[g & 7];
        if (g < DEP - 8) { b1[g & 7] = *f1; f1 += ws; b2[g & 7] = *f2; f2 += ws; }
        ull W1 = pack2(c1), W2 = pack2(c2);
        const double2* sp = reinterpret_cast<const double2*>(sA[g]);
        double2 q0 = sp[0], q1 = sp[1];
        ull s0 = __double_as_longlong(q0.x);
        ull s1 = __double_as_longlong(q0.y);
        ull s2 = __double_as_longlong(q1.x);
        ull s3 = __double_as_longlong(q1.y);
        ffma2(a1[0], s0, W1); ffma2(a1[1], s1, W1);
        ffma2(a1[2], s2, W1); ffma2(a1[3], s3, W1);
        ffma2(a2[0], s0, W2); ffma2(a2[1], s1, W2);
        ffma2(a2[2], s2, W2); ffma2(a2[3], s3, W2);
    }
}

__device__ __forceinline__ void fill_T8(float (*dst)[8], const float* __restrict__ srcT,
                                        int bg, int hbase) {
    for (int idx = threadIdx.x; idx < DEP * 8; idx += NTHR) {
        int hh = idx >> 3, bb = idx & 7;
        dst[hh][bb] = srcT[(hbase + hh) * kB + bg * 8 + bb];
    }
}

// ---- A tile: jointT @ Wc -> d_part ----
__device__ void A_tile(int tt, float (*sA)[8], const float* __restrict__ Wc) {
    int hs = tt & 7, vch = (tt >> 3) % 10, bg = tt / 80;
    int hbase = hs * DEP;
    fill_T8(sA, d_jointT, bg, hbase);
    __syncthreads();
    int tid = threadIdx.x;
    int v1 = vch * 512 + tid;
    int v2 = v1 + 256;
    bool ok2 = v2 < kV;
    const float* w1 = Wc + (size_t)hbase * kV + v1;
    const float* w2 = Wc + (size_t)hbase * kV + (ok2 ? v2 : v1);
    ull a1[4] = {0, 0, 0, 0}, a2[4] = {0, 0, 0, 0};
    dot80_2(a1, a2, sA, w1, w2, kV);
    size_t rb = (size_t)(hs * kB + bg * 8) * kV;
#pragma unroll
    for (int i = 0; i < 4; i++) {
        float2 f = unpack2(a1[i]);
        d_part[rb + (size_t)(2 * i) * kV + v1] = f.x;
        d_part[rb + (size_t)(2 * i + 1) * kV + v1] = f.y;
    }
    if (ok2) {
#pragma unroll
        for (int i = 0; i < 4; i++) {
            float2 f = unpack2(a2[i]);
            d_part[rb + (size_t)(2 * i) * kV + v2] = f.x;
            d_part[rb + (size_t)(2 * i + 1) * kV + v2] = f.y;
        }
    }
}

// ---- CH tile: hT @ Wh -> d_gpart ----
__device__ void CH_tile(int u, float (*sA)[8], const float* __restrict__ Wh) {
    int hs = u & 7, jch = (u >> 3) % 5, bg = u / 40;
    int hbase = hs * DEP;
    fill_T8(sA, d_hT, bg, hbase);
    __syncthreads();
    int tid = threadIdx.x;
    int j1 = jch * 512 + tid;
    int j2 = j1 + 256;
    const float* w1 = Wh + (size_t)hbase * kG + j1;
    const float* w2 = Wh + (size_t)hbase * kG + j2;
    ull a1[4] = {0, 0, 0, 0}, a2[4] = {0, 0, 0, 0};
    dot80_2(a1, a2, sA, w1, w2, kG);
    int g1 = j1 / kH, k1 = j1 - g1 * kH;
    int g2 = j2 / kH, k2 = j2 - g2 * kH;
#pragma unroll
    for (int i = 0; i < 4; i++) {
        float2 f = unpack2(a1[i]);
        d_gpart[(((size_t)hs * kB + bg * 8 + 2 * i) * kH + k1) * 4 + g1] = f.x;
        d_gpart[(((size_t)hs * kB + bg * 8 + 2 * i + 1) * kH + k1) * 4 + g1] = f.y;
    }
#pragma unroll
    for (int i = 0; i < 4; i++) {
        float2 f = unpack2(a2[i]);
        d_gpart[(((size_t)hs * kB + bg * 8 + 2 * i) * kH + k2) * 4 + g2] = f.x;
        d_gpart[(((size_t)hs * kB + bg * 8 + 2 * i + 1) * kH + k2) * 4 + g2] = f.y;
    }
}

// ---- B unit (b, vb): argmax + sumexp over v in [512vb, 512vb+512) ----
__device__ void B_unit(int b, int vb, const float* __restrict__ bc,
                       float* s_f, int* s_i, float* s_s, int p) {
    int tid = threadIdx.x;
    float m = -1e30f; int mi = 0x7fffffff; float se = 0.f;
    int v = vb * 512 + 4 * tid;
    if (tid < 128 && v + 3 < kV) {
        float4 s = *(const float4*)&bc[v];
#pragma unroll
        for (int hs = 0; hs < HS; hs++) {
            float4 pp = *(const float4*)&d_part[((size_t)(hs * kB + b)) * kV + v];
            s.x += pp.x; s.y += pp.y; s.z += pp.z; s.w += pp.w;
        }
        se = expf(s.x) + expf(s.y) + expf(s.z) + expf(s.w);
        m = s.x; mi = v;
        if (s.y > m) { m = s.y; mi = v + 1; }
        if (s.z > m) { m = s.z; mi = v + 2; }
        if (s.w > m) { m = s.w; mi = v + 3; }
    }
#pragma unroll
    for (int o = 16; o; o >>= 1) {
        float om = __shfl_down_sync(0xffffffffu, m, o);
        int oi = __shfl_down_sync(0xffffffffu, mi, o);
        float os = __shfl_down_sync(0xffffffffu, se, o);
        if (om > m || (om == m && oi < mi)) { m = om; mi = oi; }
        se += os;
    }
    int wid = tid >> 5;
    if ((tid & 31) == 0) { s_f[wid] = m; s_i[wid] = mi; s_s[wid] = se; }
    __syncthreads();
    if (tid == 0) {
        float S = se;
#pragma unroll
        for (int w = 1; w < 4; w++) {        // only warps 0-3 carry data (tid<128)
            float om = s_f[w]; int oi = s_i[w];
            if (om > m || (om == m && oi < mi)) { m = om; mi = oi; }
            S += s_s[w];
        }
        int u = b * 10 + vb;
        d_bmax[u] = m; d_bidx[u] = mi; d_bsum[u] = S;
        __threadfence();
        atomicAdd(&f_b[p][b][0], 1u);
    }
}

// ---- C2 unit (b, kq): combine + LSTM over k in [160kq,160kq+160) + emit ----
__device__ void C2_unit(int t, int b, int kq, const float* __restrict__ tn,
                        const float* __restrict__ bias, float* __restrict__ out,
                        float* s_f, int* s_i, float* s_s, int p) {
    int tid = threadIdx.x;
    // combine 10 partials (tid 0), broadcast via smem
    if (tid == 0) {
        float M = -1e30f; int MI = 0; float S = 0.f;
#pragma unroll
        for (int c = 0; c < 10; c++) {
            float cm = __ldcg(&d_bmax[b * 10 + c]);
            int ci = __ldcg(&d_bidx[b * 10 + c]);
            S += __ldcg(&d_bsum[b * 10 + c]);
            if (cm > M) { M = cm; MI = ci; }
        }
        s_f[0] = M; s_i[0] = MI; s_s[0] = S;
    }
    __syncthreads();
    float M = s_f[0]; int MI = s_i[0]; float S = s_s[0];
    int upd = (MI != 0);
    int nt = upd ? MI : d_tok[b];

    if (t < kT - 1) {
        wait_cnt(&f_gp[p][0], 160u);
        if (tid < 160) {
            int k = kq * 160 + tid;
            float hnew;
            if (upd) {
                float4 a = *(const float4*)&d_xwx[((size_t)nt * kH + k) * 4];
                a.x += bias[k]; a.y += bias[kH + k];
                a.z += bias[2 * kH + k]; a.w += bias[3 * kH + k];
#pragma unroll
                for (int hs = 0; hs < HS; hs++) {
                    float4 pp = *(const float4*)&d_gpart[(((size_t)hs * kB + b) * kH + k) * 4];
                    a.x += pp.x; a.y += pp.y; a.z += pp.z; a.w += pp.w;
                }
                float cold = d_c[b * kH + k];
                float c2 = sigf(a.y) * cold + sigf(a.x) * tanhf(a.z);
                float h2 = sigf(a.w) * tanhf(c2);
                d_c[b * kH + k] = c2;
                d_hT[k * kB + b] = h2;
                hnew = h2;
            } else {
                hnew = d_hT[k * kB + b];
            }
            d_jointT[k * kB + b] = tanhf(tn[((size_t)b * kT + (t + 1)) * kH + k] + hnew);
        }
    }

    if (kq == 0 && tid == 0) {
        float val = M - logf(S);
        float sc = d_scores[b] + (upd ? val : 0.f);
        d_scores[b] = sc;
        if (t == kT - 1) out[b] = sc;
        out[kB + (size_t)b * kT + t] = (float)(upd ? MI : 0);
        if (upd) d_tok[b] = MI;
    }

    if (t < kT - 1) {
        __syncthreads();
        if (tid == 0) {
            __threadfence();
            int q = p ^ 1;
            atomicAdd(&f_joint[q][(2 * kq) * 4 + (b >> 3)][0], 1u);
            atomicAdd(&f_joint[q][(2 * kq + 1) * 4 + (b >> 3)][0], 1u);
        }
    }
}

// ---- one-time: xWx = embed @ Wx -> [v][k][gate] ----
__device__ void precompute_xwx(const float* __restrict__ embed, const float* __restrict__ Wx,
                               float (*sA)[8]) {
    for (int tp = blockIdx.x; tp < PT; tp += NBLK) {
        int rb = tp / 5, jch = tp % 5;
        int v0 = rb * 8;
        int tid = threadIdx.x;
        int j1 = jch * 512 + tid, j2 = j1 + 256;
        ull a1[4] = {0, 0, 0, 0}, a2[4] = {0, 0, 0, 0};
        for (int hs = 0; hs < HS; hs++) {
            __syncthreads();
            for (int idx = tid; idx < DEP * 8; idx += NTHR) {
                int hh = idx >> 3, bb = idx & 7;
                sA[hh][bb] = embed[(size_t)(v0 + bb) * kH + hs * DEP + hh];
            }
            __syncthreads();
            dot80_2(a1, a2, sA, Wx + (size_t)(hs * DEP) * kG + j1,
                    Wx + (size_t)(hs * DEP) * kG + j2, kG);
        }
        int g1 = j1 / kH, k1 = j1 - g1 * kH;
        int g2 = j2 / kH, k2 = j2 - g2 * kH;
#pragma unroll
        for (int i = 0; i < 4; i++) {
            float2 f1 = unpack2(a1[i]);
            float2 f2 = unpack2(a2[i]);
            d_xwx[((size_t)(v0 + 2 * i) * kH + k1) * 4 + g1] = f1.x;
            d_xwx[((size_t)(v0 + 2 * i + 1) * kH + k1) * 4 + g1] = f1.y;
            d_xwx[((size_t)(v0 + 2 * i) * kH + k2) * 4 + g2] = f2.x;
            d_xwx[((size_t)(v0 + 2 * i + 1) * kH + k2) * 4 + g2] = f2.y;
        }
        __syncthreads();
    }
}

__device__ void initC2(const float* __restrict__ tn, const float* __restrict__ bias) {
    int gid = blockIdx.x * NTHR + threadIdx.x;
    // zero all dataflow counters (both parities)
    if (gid < 2 * 32 * 32) (&f_joint[0][0][0])[gid] = 0u;
    if (gid < 2 * 10 * 32) (&f_part[0][0][0])[gid] = 0u;
    if (gid < 2 * 32)      (&f_gp[0][0])[gid] = 0u;
    if (gid < 2 * 32 * 32) (&f_b[0][0][0])[gid] = 0u;
    if (gid >= kB * kH) return;
    int b = gid / kH, k = gid - b * kH;
    float4 a = *(const float4*)&d_xwx[(size_t)k * 4];
    a.x += bias[k]; a.y += bias[kH + k]; a.z += bias[2 * kH + k]; a.w += bias[3 * kH + k];
    float c1 = sigf(a.x) * tanhf(a.z);
    float h1 = sigf(a.w) * tanhf(c1);
    d_c[gid] = c1;
    d_hT[k * kB + b] = h1;
    d_jointT[k * kB + b] = tanhf(tn[(size_t)b * kT * kH + k] + h1);
    if (k == 0) { d_scores[b] = 0.f; d_tok[b] = 0; }
}

__global__ void __launch_bounds__(NTHR, 4)
transducer_kernel(const float* __restrict__ tn, const float* __restrict__ embed,
                  const float* __restrict__ Wx, const float* __restrict__ Wh,
                  const float* __restrict__ bias, const float* __restrict__ Wc,
                  const float* __restrict__ bc, float* __restrict__ out) {
    __shared__ __align__(16) float sA[DEP][8];
    __shared__ float s_f[8];
    __shared__ int   s_i[8];
    __shared__ float s_s[8];

    precompute_xwx(embed, Wx, sA);
    grid_barrier();
    initC2(tn, bias);
    grid_barrier();

    int i = blockIdx.x;
    for (int t = 0; t < kT; ++t) {
        int p = t & 1;
        if (i < 320) {
            // stale-parity resets (before any work; downstream arrivals ordered after)
            if (threadIdx.x == 0) {
                if (i < 32) atomicExch(&f_joint[p ^ 1][i][0], 0u);
                else if (i < 42) atomicExch(&f_part[p ^ 1][i - 32][0], 0u);
                else if (i == 42) atomicExch(&f_gp[p ^ 1][0], 0u);
            }
            // A tile
            int hs = i & 7, bg = i / 80;
            if (t > 0) wait_cnt(&f_joint[p][hs * 4 + bg][0], 8u);
            else __syncthreads();
            A_tile(i, sA, Wc);
            __syncthreads();
            if (threadIdx.x == 0) {
                __threadfence();
                atomicAdd(&f_part[p][(i >> 3) % 10][0], 1u);
            }
            __syncthreads();
            // B unit
            int b = i / 10, vb = i % 10;
            wait_cnt(&f_part[p][vb][0], 32u);
            B_unit(b, vb, bc, s_f, s_i, s_s, p);
        } else {
            int u = i - 320;
            int b = u >> 2, kq = u & 3;
            if (threadIdx.x == 0 && u < 128 && kq == 0)
                atomicExch(&f_b[p ^ 1][b][0], 0u);
            if (t < kT - 1) {
                int hs = u & 7, bg = u / 40;
                if (t > 0) wait_cnt(&f_joint[p][hs * 4 + bg][0], 8u);
                else __syncthreads();
                CH_tile(u, sA, Wh);
                arrive_cnt(&f_gp[p][0]);
            }
            if (u < 128) {
                wait_cnt(&f_b[p][b][0], 10u);
                C2_unit(t, b, kq, tn, bias, out, s_f, s_i, s_s, p);
            }
        }
        grid_barrier();
    }
}

extern "C" void kernel_launch(void* const* d_in, const int* in_sizes, int n_in,
                              void* d_out, int out_size) {
    const float* tn    = (const float*)d_in[0];
    const float* embed = (const float*)d_in[1];
    const float* Wx    = (const float*)d_in[2];
    const float* Wh    = (const float*)d_in[3];
    const float* bias  = (const float*)d_in[4];
    const float* Wc    = (const float*)d_in[5];
    const float* bc    = (const float*)d_in[6];
    float* out = (float*)d_out;
    (void)in_sizes; (void)n_in; (void)out_size;
    transducer_kernel<<<NBLK, NTHR>>>(tn, embed, Wx, Wh, bias, Wc, bc, out);
}